// round 1
// baseline (speedup 1.0000x reference)
#include <cuda_runtime.h>

// Problem geometry (fixed by the reference):
// heads: (B=8, H=16, T=4096, D=128) float32
// anchor = head 0, others = heads 1..14 (14 heads), mean over (8,14,4096) of 1 - cos_sim
#define B_DIM 8
#define H_DIM 16
#define T_DIM 4096
#define D_DIM 128
#define N_OTHERS 14

#define WARPS_PER_BLOCK 8
#define THREADS_PER_BLOCK (WARPS_PER_BLOCK * 32)
#define N_WARP_TASKS (B_DIM * T_DIM)                     // 32768 (b,t) pairs
#define N_BLOCKS (N_WARP_TASKS / WARPS_PER_BLOCK)        // 4096
#define N_ROWS_TOTAL (B_DIM * N_OTHERS * T_DIM)          // 458752 rows averaged

#define EPS 1e-8f

// scratch for deterministic two-stage reduction (no atomics)
__device__ float g_partials[N_BLOCKS];

__device__ __forceinline__ float warp_reduce_sum(float v) {
    #pragma unroll
    for (int off = 16; off > 0; off >>= 1)
        v += __shfl_xor_sync(0xFFFFFFFFu, v, off);
    return v;
}

__global__ void __launch_bounds__(THREADS_PER_BLOCK)
cos_dissim_kernel(const float* __restrict__ heads) {
    const int warp = blockIdx.x * WARPS_PER_BLOCK + (threadIdx.x >> 5);
    const int lane = threadIdx.x & 31;

    const int b = warp >> 12;           // warp / 4096
    const int t = warp & (T_DIM - 1);   // warp % 4096

    // Row start for (b, h=0, t): ((b*16 + 0)*4096 + t)*128 floats.
    // Each lane owns one float4 (4 consecutive floats).
    const float4* base = reinterpret_cast<const float4*>(
        heads + (((size_t)b * H_DIM) * T_DIM + t) * D_DIM) + lane;

    // stride between consecutive heads, in float4 units: 4096*128/4
    const size_t h_stride4 = (size_t)T_DIM * D_DIM / 4;  // 131072

    // Anchor (head 0), loaded once per warp.
    float4 a = base[0];

    // Front-batch all 14 others-loads for max MLP.
    float4 o[N_OTHERS];
    #pragma unroll
    for (int h = 0; h < N_OTHERS; h++)
        o[h] = base[(size_t)(h + 1) * h_stride4];

    // anchor norm^2 (warp-wide)
    float na2 = a.x * a.x + a.y * a.y + a.z * a.z + a.w * a.w;
    na2 = warp_reduce_sum(na2);

    float local = 0.0f;
    #pragma unroll
    for (int h = 0; h < N_OTHERS; h++) {
        float4 v = o[h];
        float dot = v.x * a.x + v.y * a.y + v.z * a.z + v.w * a.w;
        float no2 = v.x * v.x + v.y * v.y + v.z * v.z + v.w * v.w;
        // joint butterfly reduce
        #pragma unroll
        for (int off = 16; off > 0; off >>= 1) {
            dot += __shfl_xor_sync(0xFFFFFFFFu, dot, off);
            no2 += __shfl_xor_sync(0xFFFFFFFFu, no2, off);
        }
        float denom = fmaxf(sqrtf(no2 * na2), EPS);
        local += 1.0f - dot / denom;
    }

    // block reduction: lane 0 of each warp deposits, warp 0 sums
    __shared__ float s_warp[WARPS_PER_BLOCK];
    if (lane == 0) s_warp[threadIdx.x >> 5] = local;
    __syncthreads();
    if (threadIdx.x == 0) {
        float s = 0.0f;
        #pragma unroll
        for (int w = 0; w < WARPS_PER_BLOCK; w++) s += s_warp[w];
        g_partials[blockIdx.x] = s;
    }
}

__global__ void __launch_bounds__(1024)
final_reduce_kernel(float* __restrict__ out) {
    __shared__ float s[1024];
    float acc = 0.0f;
    for (int i = threadIdx.x; i < N_BLOCKS; i += 1024)
        acc += g_partials[i];
    s[threadIdx.x] = acc;
    __syncthreads();
    #pragma unroll
    for (int stride = 512; stride > 0; stride >>= 1) {
        if (threadIdx.x < stride) s[threadIdx.x] += s[threadIdx.x + stride];
        __syncthreads();
    }
    if (threadIdx.x == 0)
        out[0] = s[0] * (1.0f / (float)N_ROWS_TOTAL);
}

extern "C" void kernel_launch(void* const* d_in, const int* in_sizes, int n_in,
                              void* d_out, int out_size) {
    const float* heads = (const float*)d_in[0];
    float* out = (float*)d_out;

    cos_dissim_kernel<<<N_BLOCKS, THREADS_PER_BLOCK>>>(heads);
    final_reduce_kernel<<<1, 1024>>>(out);
}

// round 2
// speedup vs baseline: 1.2684x; 1.2684x over previous
#include <cuda_runtime.h>

// heads: (B=8, H=16, T=4096, D=128) float32
// anchor = head 0, others = heads 1..14, mean over (8,14,4096) of 1 - cos_sim
#define B_DIM 8
#define H_DIM 16
#define T_DIM 4096
#define D_DIM 128
#define N_OTHERS 14

#define TASKS_PER_WARP 4            // 4 (b,t) tasks per warp, 8 lanes each
#define WARPS_PER_BLOCK 8
#define THREADS_PER_BLOCK (WARPS_PER_BLOCK * 32)
#define N_TASKS (B_DIM * T_DIM)                           // 32768
#define N_WARPS (N_TASKS / TASKS_PER_WARP)                // 8192
#define N_BLOCKS (N_WARPS / WARPS_PER_BLOCK)              // 1024
#define N_ROWS_TOTAL (B_DIM * N_OTHERS * T_DIM)           // 458752

#define EPS 1e-8f

__device__ float g_partials[N_BLOCKS];
__device__ unsigned int g_count = 0;

__device__ __forceinline__ float4 ldcs4(const float4* p) {
    return __ldcs(p);
}

__global__ void __launch_bounds__(THREADS_PER_BLOCK)
cos_dissim_kernel(const float* __restrict__ heads, float* __restrict__ out) {
    const int warp = blockIdx.x * WARPS_PER_BLOCK + (threadIdx.x >> 5);
    const int lane = threadIdx.x & 31;
    const int s    = lane & 7;        // sub-lane within 8-lane group

    // task id for this lane's group
    const int task = warp * TASKS_PER_WARP + (lane >> 3);
    const int b = task >> 12;                 // task / 4096
    const int t = task & (T_DIM - 1);         // task % 4096

    // Row start (float4 units) for (b, h, t): ((b*16 + h)*4096 + t) * 32
    // Lane s owns float4 indices {s, s+8, s+16, s+24} of the 32-float4 row.
    const float4* base = reinterpret_cast<const float4*>(heads)
                       + (((size_t)b * H_DIM) * T_DIM + t) * (D_DIM / 4) + s;
    const size_t h_stride4 = (size_t)T_DIM * (D_DIM / 4);   // 131072

    // ---- anchor (head 0): 16 floats per lane ----
    float4 a0 = ldcs4(base + 0);
    float4 a1 = ldcs4(base + 8);
    float4 a2 = ldcs4(base + 16);
    float4 a3 = ldcs4(base + 24);

    float na2 = a0.x*a0.x + a0.y*a0.y + a0.z*a0.z + a0.w*a0.w
              + a1.x*a1.x + a1.y*a1.y + a1.z*a1.z + a1.w*a1.w
              + a2.x*a2.x + a2.y*a2.y + a2.z*a2.z + a2.w*a2.w
              + a3.x*a3.x + a3.y*a3.y + a3.z*a3.z + a3.w*a3.w;
    #pragma unroll
    for (int off = 4; off > 0; off >>= 1)
        na2 += __shfl_xor_sync(0xFFFFFFFFu, na2, off);

    // ---- head loop with 2-deep double buffer for MLP ----
    float local = 0.0f;

    const float4* p = base + h_stride4;       // head 1
    float4 v0 = ldcs4(p + 0), v1 = ldcs4(p + 8), v2 = ldcs4(p + 16), v3 = ldcs4(p + 24);

    #pragma unroll
    for (int h = 1; h <= N_OTHERS; h++) {
        float4 w0, w1, w2, w3;
        if (h < N_OTHERS) {
            const float4* q = base + (size_t)(h + 1) * h_stride4;
            w0 = ldcs4(q + 0); w1 = ldcs4(q + 8); w2 = ldcs4(q + 16); w3 = ldcs4(q + 24);
        }

        float dot = v0.x*a0.x + v0.y*a0.y + v0.z*a0.z + v0.w*a0.w
                  + v1.x*a1.x + v1.y*a1.y + v1.z*a1.z + v1.w*a1.w
                  + v2.x*a2.x + v2.y*a2.y + v2.z*a2.z + v2.w*a2.w
                  + v3.x*a3.x + v3.y*a3.y + v3.z*a3.z + v3.w*a3.w;
        float no2 = v0.x*v0.x + v0.y*v0.y + v0.z*v0.z + v0.w*v0.w
                  + v1.x*v1.x + v1.y*v1.y + v1.z*v1.z + v1.w*v1.w
                  + v2.x*v2.x + v2.y*v2.y + v2.z*v2.z + v2.w*v2.w
                  + v3.x*v3.x + v3.y*v3.y + v3.z*v3.z + v3.w*v3.w;

        #pragma unroll
        for (int off = 4; off > 0; off >>= 1) {
            dot += __shfl_xor_sync(0xFFFFFFFFu, dot, off);
            no2 += __shfl_xor_sync(0xFFFFFFFFu, no2, off);
        }

        float denom = fmaxf(sqrtf(no2 * na2), EPS);
        local += 1.0f - dot / denom;

        v0 = w0; v1 = w1; v2 = w2; v3 = w3;
    }

    // keep one copy per task (group leader), then fold 4 groups -> lane 0
    if (s != 0) local = 0.0f;
    local += __shfl_xor_sync(0xFFFFFFFFu, local, 8);
    local += __shfl_xor_sync(0xFFFFFFFFu, local, 16);

    __shared__ float s_warp[WARPS_PER_BLOCK];
    __shared__ bool s_is_last;
    if (lane == 0) s_warp[threadIdx.x >> 5] = local;
    __syncthreads();

    if (threadIdx.x == 0) {
        float sum = 0.0f;
        #pragma unroll
        for (int w = 0; w < WARPS_PER_BLOCK; w++) sum += s_warp[w];
        g_partials[blockIdx.x] = sum;
        __threadfence();
        unsigned int old = atomicAdd(&g_count, 1u);
        s_is_last = (old == (unsigned int)(N_BLOCKS - 1));
    }
    __syncthreads();

    // ---- last block folds all partials (fixed order -> deterministic) ----
    if (s_is_last) {
        __shared__ float s_red[THREADS_PER_BLOCK];
        float acc = 0.0f;
        #pragma unroll
        for (int i = threadIdx.x; i < N_BLOCKS; i += THREADS_PER_BLOCK)
            acc += g_partials[i];
        s_red[threadIdx.x] = acc;
        __syncthreads();
        #pragma unroll
        for (int stride = THREADS_PER_BLOCK / 2; stride >= 32; stride >>= 1) {
            if (threadIdx.x < stride) s_red[threadIdx.x] += s_red[threadIdx.x + stride];
            __syncthreads();
        }
        if (threadIdx.x < 32) {
            float v = s_red[threadIdx.x];
            #pragma unroll
            for (int off = 16; off > 0; off >>= 1)
                v += __shfl_xor_sync(0xFFFFFFFFu, v, off);
            if (threadIdx.x == 0) {
                out[0] = v * (1.0f / (float)N_ROWS_TOTAL);
                g_count = 0;   // reset for next graph replay
            }
        }
    }
}

extern "C" void kernel_launch(void* const* d_in, const int* in_sizes, int n_in,
                              void* d_out, int out_size) {
    const float* heads = (const float*)d_in[0];
    float* out = (float*)d_out;
    cos_dissim_kernel<<<N_BLOCKS, THREADS_PER_BLOCK>>>(heads, out);
}

// round 3
// speedup vs baseline: 1.2937x; 1.0199x over previous
#include <cuda_runtime.h>

// heads: (B=8, H=16, T=4096, D=128) float32
// anchor = head 0, others = heads 1..14, mean over (8,14,4096) of 1 - cos_sim
#define B_DIM 8
#define H_DIM 16
#define T_DIM 4096
#define D_DIM 128
#define N_OTHERS 14

#define TASKS_PER_WARP 4            // 4 (b,t) tasks per warp, 8 lanes each
#define WARPS_PER_BLOCK 4           // smaller blocks -> finer tail granularity
#define THREADS_PER_BLOCK (WARPS_PER_BLOCK * 32)   // 128
#define N_TASKS (B_DIM * T_DIM)                           // 32768
#define N_WARPS (N_TASKS / TASKS_PER_WARP)                // 8192
#define N_BLOCKS (N_WARPS / WARPS_PER_BLOCK)              // 2048
#define N_ROWS_TOTAL (B_DIM * N_OTHERS * T_DIM)           // 458752

#define EPS 1e-8f

__device__ float g_partials[N_BLOCKS];
__device__ unsigned int g_count = 0;

__device__ __forceinline__ float4 ldcs4(const float4* p) {
    return __ldcs(p);
}

__global__ void __launch_bounds__(THREADS_PER_BLOCK)
cos_dissim_kernel(const float* __restrict__ heads, float* __restrict__ out) {
    const int warp = blockIdx.x * WARPS_PER_BLOCK + (threadIdx.x >> 5);
    const int lane = threadIdx.x & 31;
    const int s    = lane & 7;        // sub-lane within 8-lane group

    const int task = warp * TASKS_PER_WARP + (lane >> 3);
    const int b = task >> 12;                 // task / 4096
    const int t = task & (T_DIM - 1);         // task % 4096

    // Row start (float4 units) for (b, h, t): ((b*16 + h)*4096 + t) * 32
    // Lane s owns float4 indices {s, s+8, s+16, s+24}.
    const float4* base = reinterpret_cast<const float4*>(heads)
                       + (((size_t)b * H_DIM) * T_DIM + t) * (D_DIM / 4) + s;
    const size_t h_stride4 = (size_t)T_DIM * (D_DIM / 4);   // 131072

    // ---- anchor (head 0): 16 floats per lane ----
    float4 a0 = ldcs4(base + 0);
    float4 a1 = ldcs4(base + 8);
    float4 a2 = ldcs4(base + 16);
    float4 a3 = ldcs4(base + 24);

    float na2 = a0.x*a0.x + a0.y*a0.y + a0.z*a0.z + a0.w*a0.w
              + a1.x*a1.x + a1.y*a1.y + a1.z*a1.z + a1.w*a1.w
              + a2.x*a2.x + a2.y*a2.y + a2.z*a2.z + a2.w*a2.w
              + a3.x*a3.x + a3.y*a3.y + a3.z*a3.z + a3.w*a3.w;
    #pragma unroll
    for (int off = 4; off > 0; off >>= 1)
        na2 += __shfl_xor_sync(0xFFFFFFFFu, na2, off);

    // ---- head loop, 2-deep double buffer ----
    float local = 0.0f;

    const float4* p = base + h_stride4;       // head 1
    float4 v0 = ldcs4(p + 0), v1 = ldcs4(p + 8), v2 = ldcs4(p + 16), v3 = ldcs4(p + 24);

    #pragma unroll
    for (int h = 1; h <= N_OTHERS; h++) {
        float4 w0, w1, w2, w3;
        if (h < N_OTHERS) {
            const float4* q = base + (size_t)(h + 1) * h_stride4;
            w0 = ldcs4(q + 0); w1 = ldcs4(q + 8); w2 = ldcs4(q + 16); w3 = ldcs4(q + 24);
        }

        float dot = v0.x*a0.x + v0.y*a0.y + v0.z*a0.z + v0.w*a0.w
                  + v1.x*a1.x + v1.y*a1.y + v1.z*a1.z + v1.w*a1.w
                  + v2.x*a2.x + v2.y*a2.y + v2.z*a2.z + v2.w*a2.w
                  + v3.x*a3.x + v3.y*a3.y + v3.z*a3.z + v3.w*a3.w;
        float no2 = v0.x*v0.x + v0.y*v0.y + v0.z*v0.z + v0.w*v0.w
                  + v1.x*v1.x + v1.y*v1.y + v1.z*v1.z + v1.w*v1.w
                  + v2.x*v2.x + v2.y*v2.y + v2.z*v2.z + v2.w*v2.w
                  + v3.x*v3.x + v3.y*v3.y + v3.z*v3.z + v3.w*v3.w;

        #pragma unroll
        for (int off = 4; off > 0; off >>= 1) {
            dot += __shfl_xor_sync(0xFFFFFFFFu, dot, off);
            no2 += __shfl_xor_sync(0xFFFFFFFFu, no2, off);
        }

        float denom = fmaxf(sqrtf(no2 * na2), EPS);
        local += 1.0f - dot / denom;

        v0 = w0; v1 = w1; v2 = w2; v3 = w3;
    }

    // one copy per task (group leader), fold 4 groups -> lane 0
    if (s != 0) local = 0.0f;
    local += __shfl_xor_sync(0xFFFFFFFFu, local, 8);
    local += __shfl_xor_sync(0xFFFFFFFFu, local, 16);

    __shared__ float s_warp[WARPS_PER_BLOCK];
    __shared__ bool s_is_last;
    if (lane == 0) s_warp[threadIdx.x >> 5] = local;
    __syncthreads();

    if (threadIdx.x == 0) {
        float sum = 0.0f;
        #pragma unroll
        for (int w = 0; w < WARPS_PER_BLOCK; w++) sum += s_warp[w];
        g_partials[blockIdx.x] = sum;
        __threadfence();
        unsigned int old = atomicAdd(&g_count, 1u);
        s_is_last = (old == (unsigned int)(N_BLOCKS - 1));
    }
    __syncthreads();

    // ---- last block folds all partials (fixed order -> deterministic) ----
    if (s_is_last) {
        __shared__ float s_red[THREADS_PER_BLOCK];
        float acc = 0.0f;
        #pragma unroll
        for (int i = threadIdx.x; i < N_BLOCKS; i += THREADS_PER_BLOCK)
            acc += g_partials[i];
        s_red[threadIdx.x] = acc;
        __syncthreads();
        #pragma unroll
        for (int stride = THREADS_PER_BLOCK / 2; stride >= 32; stride >>= 1) {
            if (threadIdx.x < stride) s_red[threadIdx.x] += s_red[threadIdx.x + stride];
            __syncthreads();
        }
        if (threadIdx.x < 32) {
            float v = s_red[threadIdx.x];
            #pragma unroll
            for (int off = 16; off > 0; off >>= 1)
                v += __shfl_xor_sync(0xFFFFFFFFu, v, off);
            if (threadIdx.x == 0) {
                out[0] = v * (1.0f / (float)N_ROWS_TOTAL);
                g_count = 0;   // reset for next graph replay
            }
        }
    }
}

extern "C" void kernel_launch(void* const* d_in, const int* in_sizes, int n_in,
                              void* d_out, int out_size) {
    const float* heads = (const float*)d_in[0];
    float* out = (float*)d_out;
    cos_dissim_kernel<<<N_BLOCKS, THREADS_PER_BLOCK>>>(heads, out);
}